// round 12
// baseline (speedup 1.0000x reference)
#include <cuda_runtime.h>
#include <math.h>

#define BB 4
#define CC 64
#define HH 64
#define WW 64
#define LL 4096      // H*W
#define PW 66        // padded width/height
#define LP 4356      // 66*66 padded pixels
#define BSTRIDE 72   // band-row stride (floats), 16B-aligned window
#define BFLOATS (66*BSTRIDE)   // 4752 floats per band slot
#define NSP 8        // stopk key-range splits per batch
#define TILES 8      // key tiles per stopk block (64/NSP)

// ---------------- persistent device scratch ----------------
__device__ __align__(16) float g_xpadR[BB*CC*LP];     // reflect-padded x
__device__ __align__(16) float g_xpadZ[BB*CC*LP];     // zero-padded x (borders stay 0)
__device__ __align__(16) float g_reluZ[BB*CC*LP];     // zero-padded relu(conv1)
__device__ __align__(16) float g_G[(size_t)BB*LP*LP + 16]; // pixel gram
__device__ float g_n2[BB*LP];                         // per-pixel squared channel norms
__device__ float g_rn[BB*LL];                         // reciprocal patch norms
__device__ float g_feature[BB*CC*HH*WW];
__device__ float g_topv[BB*4*LL];
__device__ int   g_topi[BB*4*LL];
__device__ float g_pmv[(size_t)BB*NSP*5*LL];          // split-K partial top-5 values
__device__ int   g_pmi[(size_t)BB*NSP*5*LL];          // split-K partial top-5 indices

__device__ __forceinline__ int refl(int t){ return t < 0 ? -t : (t >= 64 ? 126 - t : t); }

// ---------------- K1: build reflect- and zero-padded inputs ----------------
__global__ void pad_kernel(const float* __restrict__ x){
    int b  = blockIdx.y;
    int pr = blockIdx.x;                 // 0..65
    int sr = refl(pr - 1);
    bool rin = (pr >= 1 && pr <= 64);
    for (int e = threadIdx.x; e < CC*PW; e += blockDim.x){
        int c = e / PW, pc = e % PW;
        int sc = refl(pc - 1);
        float v = x[((b*CC + c)*HH + sr)*WW + sc];
        g_xpadR[(b*CC + c)*LP + pr*PW + pc] = v;
        if (rin && pc >= 1 && pc <= 64)
            g_xpadZ[(b*CC + c)*LP + pr*PW + pc] = v;
    }
}

// ---------------- K2: 3x3 conv (zero pad), round-4 form ----------------
__global__ __launch_bounds__(256, 2) void convg_kernel(const float* __restrict__ w,
                                                       const float* __restrict__ bias,
                                                       int mode){
    extern __shared__ float cs[];
    float* s   = cs;            // [64][3][68]
    float* wsm = cs + 13056;    // [64co][16ci][9]
    int li = blockIdx.x, b = blockIdx.y;
    const float* in = (mode == 0) ? g_xpadZ : g_reluZ;
    const float* ib = in + (size_t)b*CC*LP;
    int t = threadIdx.x;

    for (int e = t; e < 64*3*33; e += 256){
        int ci = e / 99; int rem = e % 99; int r = rem / 33; int c2 = rem % 33;
        *(float2*)&s[(ci*3 + r)*68 + c2*2] =
            *(const float2*)&ib[(size_t)ci*LP + (li + r)*PW + c2*2];
    }

    int j0 = (t & 15)*4, c0 = (t >> 4)*4;
    float acc[4][4];
    #pragma unroll
    for (int i = 0; i < 4; i++)
        #pragma unroll
        for (int j = 0; j < 4; j++) acc[i][j] = 0.f;

    for (int cc = 0; cc < 4; cc++){
        __syncthreads();
        for (int e = t; e < 9216; e += 256)
            wsm[e] = w[(e / 144)*576 + cc*144 + (e % 144)];
        __syncthreads();
        #pragma unroll 2
        for (int cil = 0; cil < 16; cil++){
            const float* sr = &s[(cc*16 + cil)*3*68];
            float p[3][6];
            #pragma unroll
            for (int r = 0; r < 3; r++){
                float4 u = *(const float4*)&sr[r*68 + j0];
                float2 v = *(const float2*)&sr[r*68 + j0 + 4];
                p[r][0]=u.x; p[r][1]=u.y; p[r][2]=u.z; p[r][3]=u.w; p[r][4]=v.x; p[r][5]=v.y;
            }
            #pragma unroll
            for (int i = 0; i < 4; i++){
                const float* wp = &wsm[(c0 + i)*144 + cil*9];
                float w0=wp[0],w1=wp[1],w2=wp[2],w3=wp[3],w4=wp[4],
                      w5=wp[5],w6=wp[6],w7=wp[7],w8=wp[8];
                #pragma unroll
                for (int j = 0; j < 4; j++)
                    acc[i][j] += p[0][j]*w0 + p[0][j+1]*w1 + p[0][j+2]*w2
                               + p[1][j]*w3 + p[1][j+1]*w4 + p[1][j+2]*w5
                               + p[2][j]*w6 + p[2][j+1]*w7 + p[2][j+2]*w8;
            }
        }
    }

    float bv[4];
    #pragma unroll
    for (int i = 0; i < 4; i++) bv[i] = __ldg(&bias[c0 + i]);
    if (mode == 0){
        #pragma unroll
        for (int i = 0; i < 4; i++)
            #pragma unroll
            for (int j = 0; j < 4; j++)
                g_reluZ[(size_t)(b*CC + c0 + i)*LP + (li + 1)*PW + (j0 + j + 1)] =
                    fmaxf(acc[i][j] + bv[i], 0.f);
    } else {
        #pragma unroll
        for (int i = 0; i < 4; i++){
            float4 o = make_float4(acc[i][0]+bv[i], acc[i][1]+bv[i],
                                   acc[i][2]+bv[i], acc[i][3]+bv[i]);
            *(float4*)&g_feature[((b*CC + c0 + i)*HH + li)*WW + j0] = o;
        }
    }
}

// ---------------- K3: pixel gram GEMM, symmetric-halved, per-batch ----------------
__global__ __launch_bounds__(256, 2) void gram_gemm(int b){
    extern __shared__ float sg[];
    float* Qs    = sg;            // [64][128]
    float* Ks    = sg + 8192;     // [64][128]
    float* stage = sg;            // alias: [128][133]
    int sIdx = blockIdx.x;
    int qt = (int)((sqrtf(8.f*sIdx + 1.f) - 1.f)*0.5f);
    while ((qt + 1)*(qt + 2)/2 <= sIdx) qt++;
    while (qt*(qt + 1)/2 > sIdx) qt--;
    int pt = sIdx - qt*(qt + 1)/2;
    int p0 = pt*128, q0 = qt*128;
    int t = threadIdx.x, ty = t >> 4, tx = t & 15;
    const float* xp = &g_xpadR[(size_t)b*CC*LP];

    for (int e = t; e < 64*128; e += 256){
        int d = e >> 7, col = e & 127;
        int p = p0 + col, q = q0 + col;
        Qs[e] = (p < LP) ? xp[(size_t)d*LP + p] : 0.f;
        Ks[e] = (q < LP) ? xp[(size_t)d*LP + q] : 0.f;
    }
    __syncthreads();

    float acc[8][8];
    #pragma unroll
    for (int i = 0; i < 8; i++)
        #pragma unroll
        for (int j = 0; j < 8; j++) acc[i][j] = 0.f;

    #pragma unroll 4
    for (int d = 0; d < 64; d++){
        float4 a0 = *(const float4*)&Qs[d*128 + ty*4];
        float4 a1 = *(const float4*)&Qs[d*128 + 64 + ty*4];
        float4 b0 = *(const float4*)&Ks[d*128 + tx*4];
        float4 b1 = *(const float4*)&Ks[d*128 + 64 + tx*4];
        float ar[8] = {a0.x,a0.y,a0.z,a0.w,a1.x,a1.y,a1.z,a1.w};
        float br[8] = {b0.x,b0.y,b0.z,b0.w,b1.x,b1.y,b1.z,b1.w};
        #pragma unroll
        for (int i = 0; i < 8; i++)
            #pragma unroll
            for (int j = 0; j < 8; j++) acc[i][j] += ar[i]*br[j];
    }

    float* Gb = &g_G[(size_t)b*LP*LP];
    #pragma unroll
    for (int i = 0; i < 8; i++){
        int p = p0 + ((i < 4) ? (ty*4 + i) : (64 + ty*4 + i - 4));
        if (p >= LP) continue;
        #pragma unroll
        for (int half = 0; half < 2; half++){
            int q = q0 + half*64 + tx*4;
            if (q + 4 <= LP){
                float4 v = make_float4(acc[i][half*4], acc[i][half*4+1],
                                       acc[i][half*4+2], acc[i][half*4+3]);
                *(float4*)&Gb[(size_t)p*LP + q] = v;
            } else {
                for (int j = 0; j < 4; j++)
                    if (q + j < LP) Gb[(size_t)p*LP + q + j] = acc[i][half*4 + j];
            }
        }
    }

    if (pt != qt){
        __syncthreads();
        #pragma unroll
        for (int i = 0; i < 8; i++){
            int pl = (i < 4) ? (ty*4 + i) : (64 + ty*4 + i - 4);
            #pragma unroll
            for (int j = 0; j < 8; j++){
                int ql = (j < 4) ? (tx*4 + j) : (64 + tx*4 + j - 4);
                stage[pl*133 + ql] = acc[i][j];
            }
        }
        __syncthreads();
        int wid = t >> 5, lane = t & 31;
        for (int r = wid; r < 128; r += 8){
            int q = q0 + r;
            if (q < LP){
                float4 o;
                o.x = stage[(lane*4 + 0)*133 + r];
                o.y = stage[(lane*4 + 1)*133 + r];
                o.z = stage[(lane*4 + 2)*133 + r];
                o.w = stage[(lane*4 + 3)*133 + r];
                *(float4*)&Gb[(size_t)q*LP + p0 + lane*4] = o;
            }
        }
    }
}

// ---------------- K4a: per-pixel squared channel norms ----------------
__global__ void n2_kernel(){
    int b = blockIdx.y;
    int p = blockIdx.x*256 + threadIdx.x;
    if (p >= LP) return;
    const float* xp = g_xpadR + (size_t)b*CC*LP + p;
    float s = 0.f;
    #pragma unroll 8
    for (int c = 0; c < CC; c++){ float v = xp[(size_t)c*LP]; s += v*v; }
    g_n2[b*LP + p] = s;
}

// ---------------- K4b: reciprocal patch norms ----------------
__global__ void rn_kernel(){
    int b = blockIdx.y, li = blockIdx.x, lj = threadIdx.x;   // 64 threads
    float s = 0.f;
    #pragma unroll
    for (int kh = 0; kh < 3; kh++)
        #pragma unroll
        for (int kw = 0; kw < 3; kw++)
            s += g_n2[b*LP + (li + kh)*PW + lj + kw];
    g_rn[b*LL + li*64 + lj] = 1.0f / fmaxf(sqrtf(s), 1e-12f);
}

// ---------------- K5a: split-K top-5, per-band cp.async pipeline, per-batch --------
// Runs immediately after gram(b) so G(b) is L2-resident. Block (li, sp): scans
// TILES key tiles. Bands streamed through 2 slots.
__global__ __launch_bounds__(256, 4) void stopk_part(int b){
    extern __shared__ float sm[];
    float* slot0 = sm;                      // [66][72]
    float* slot1 = sm + BFLOATS;            // [66][72]
    float* rnqS  = sm + 2*BFLOATS;          // [64]
    float* rnkS  = rnqS + 64;               // [64]

    int li = blockIdx.x;
    int sp = blockIdx.y;                    // 0..NSP-1
    int t  = threadIdx.x, ty = t >> 4, tx = t & 15;
    int qq = t & 63, seg = t >> 6;

    if (t < 64) rnqS[t] = g_rn[b*LL + li*64 + t];

    float tv[5]; int tix[5];
    #pragma unroll
    for (int i = 0; i < 5; i++){ tv[i] = -1e30f; tix[i] = 0; }

    const float* Gb = &g_G[(size_t)b*LP*LP];
    int lj0 = ty*4, mj0 = tx*4;

    auto prefetch = [&](int mi, int kh, float* dst){
        int col = (mi + kh)*66;
        int ab  = col & ~3;
        int rg0 = (li + kh)*66;
        for (int e = t; e < 66*18; e += 256){
            int a = e / 18, c16 = e - a*18;
            const float* src = Gb + (size_t)(rg0 + a)*LP + ab + c16*4;
            unsigned sb = (unsigned)__cvta_generic_to_shared(dst + a*BSTRIDE + c16*4);
            asm volatile("cp.async.cg.shared.global [%0], [%1], 16;" :: "r"(sb), "l"(src));
        }
        asm volatile("cp.async.commit_group;");
    };

    prefetch(sp*TILES, 0, slot0);

    for (int s = 0; s < TILES; s++){
        int mi = sp*TILES + s;
        float* c0 = (s & 1) ? slot1 : slot0;   // kh0 / kh2 slot this iter
        float* c1 = (s & 1) ? slot0 : slot1;   // kh1 slot

        float S[4][4];
        #pragma unroll
        for (int i = 0; i < 4; i++)
            #pragma unroll
            for (int j = 0; j < 4; j++) S[i][j] = 0.f;

        auto accum = [&](const float* band, int sh){
            #pragma unroll
            for (int r = 0; r < 6; r++){
                const float* rp = band + (lj0 + r)*BSTRIDE + sh + mj0;
                float2 u0 = *(const float2*)&rp[0];
                float2 u1 = *(const float2*)&rp[2];
                float2 u2 = *(const float2*)&rp[4];
                float w6[6] = {u0.x, u0.y, u1.x, u1.y, u2.x, u2.y};
                #pragma unroll
                for (int i = 0; i < 4; i++){
                    int kw = r - i;
                    if (kw >= 0 && kw <= 2){
                        S[i][0] += w6[kw];     S[i][1] += w6[kw + 1];
                        S[i][2] += w6[kw + 2]; S[i][3] += w6[kw + 3];
                    }
                }
            }
        };

        // ---- phase kh0 (band in c0) ----
        prefetch(mi, 1, c1);
        asm volatile("cp.async.wait_group 1;");
        if (t < 64) rnkS[t] = g_rn[b*LL + mi*64 + t];
        __syncthreads();
        accum(c0, ((mi + 0)*66) & 3);
        __syncthreads();
        // ---- phase kh1 (band in c1) ----
        prefetch(mi, 2, c0);
        asm volatile("cp.async.wait_group 1;");
        __syncthreads();
        accum(c1, ((mi + 1)*66) & 3);
        __syncthreads();
        // ---- phase kh2 (band in c0) ----
        if (s < TILES - 1){
            prefetch(mi + 1, 0, c1);
            asm volatile("cp.async.wait_group 1;");
        } else {
            asm volatile("cp.async.wait_group 0;");
        }
        __syncthreads();
        accum(c0, ((mi + 2)*66) & 3);
        __syncthreads();

        float* Sc = c0;
        #pragma unroll
        for (int i = 0; i < 4; i++){
            float rq = rnqS[lj0 + i];
            #pragma unroll
            for (int j = 0; j < 4; j++)
                Sc[(lj0 + i)*65 + mj0 + j] = S[i][j] * rq * rnkS[mj0 + j];
        }
        __syncthreads();

        {   // all 256 threads: query qq, keys [seg*16, seg*16+16)
            const float* rowp = &Sc[qq*65 + seg*16];
            int k0 = (mi << 6) + seg*16;
            for (int jj = 0; jj < 16; jj++){
                float sv = rowp[jj];
                if (sv > tv[4]){
                    float v0 = sv; int i0 = k0 + jj;
                    #pragma unroll
                    for (int p = 0; p < 5; p++){
                        if (v0 > tv[p]){
                            float tpv = tv[p]; int tpi = tix[p];
                            tv[p] = v0; tix[p] = i0; v0 = tpv; i0 = tpi;
                        }
                    }
                }
            }
        }
        __syncthreads();
    }

    // merge 4 segment lists per query (exact value-desc, index-asc), store top-5
    float* mv = sm;                   // [64][20]
    int*   mx = (int*)(sm + 1280);    // [64][20]
    #pragma unroll
    for (int r = 0; r < 5; r++){
        mv[qq*20 + seg*5 + r] = tv[r];
        mx[qq*20 + seg*5 + r] = tix[r];
    }
    __syncthreads();
    if (t < 64){
        unsigned used = 0;
        int l = li*64 + t;
        for (int r = 0; r < 5; r++){
            float bvv = -3e38f; int bii = 0x7fffffff; int bc = 0;
            #pragma unroll
            for (int c = 0; c < 20; c++){
                if (used & (1u << c)) continue;
                float v = mv[t*20 + c]; int ii = mx[t*20 + c];
                if (v > bvv || (v == bvv && ii < bii)){ bvv = v; bii = ii; bc = c; }
            }
            used |= 1u << bc;
            g_pmv[((size_t)(b*NSP + sp)*5 + r)*LL + l] = bvv;
            g_pmi[((size_t)(b*NSP + sp)*5 + r)*LL + l] = bii;
        }
    }
}

// ---------------- K5b: merge NSP split lists into final ranks 1..4 ----------------
// Streaming insertion: sp asc = index-asc for equal values; strict > keeps the
// earlier (smaller-index) candidate ahead -> identical to jax top_k tie order.
__global__ void topk_merge(){
    int b = blockIdx.y, li = blockIdx.x, q = threadIdx.x;  // 64 threads
    int l = li*64 + q;
    float tv[5]; int ti[5];
    #pragma unroll
    for (int i = 0; i < 5; i++){ tv[i] = -3e38f; ti[i] = 0; }
    for (int sp = 0; sp < NSP; sp++){
        #pragma unroll
        for (int r = 0; r < 5; r++){
            float v = g_pmv[((size_t)(b*NSP + sp)*5 + r)*LL + l];
            int  ix = g_pmi[((size_t)(b*NSP + sp)*5 + r)*LL + l];
            if (v > tv[4]){
                float v0 = v; int i0 = ix;
                #pragma unroll
                for (int p = 0; p < 5; p++){
                    if (v0 > tv[p]){
                        float tpv = tv[p]; int tpi = ti[p];
                        tv[p] = v0; ti[p] = i0; v0 = tpv; i0 = tpi;
                    }
                }
            }
        }
    }
    #pragma unroll
    for (int r = 1; r < 5; r++){
        g_topv[(b*4 + (r-1))*LL + l] = tv[r];
        g_topi[(b*4 + (r-1))*LL + l] = ti[r];
    }
}

// ---------------- K6: gather+fold texture, 1x1 convs, pixel-split x2 ----------------
__global__ __launch_bounds__(256, 3) void final_kernel(const float* __restrict__ x,
                             const float* __restrict__ wt1, const float* __restrict__ bt1,
                             const float* __restrict__ wt2, const float* __restrict__ bt2,
                             float* __restrict__ out){
    extern __shared__ float sm[];
    float* Tc   = sm;                    // [256][32]
    float* tex  = sm + 8192;             // [64][32]
    float* wbuf = sm + 10240;            // [64][64]
    float* msc  = sm + 14336;            // [4][32]
    int*   midx = (int*)(sm + 14464);    // [4][3][34]
    int b = blockIdx.x >> 6, i = blockIdx.x & 63;
    int h = blockIdx.y;
    int t = threadIdx.x;
    int j0 = (t & 15)*2, c0 = (t >> 4)*4;

    for (int e = t; e < 4*3*34; e += 256){
        int br = e / 102, rr = (e / 34) % 3, jo = e % 34;
        int li = i - 1 + rr, lj = h*32 - 1 + jo;
        int v = 0;
        if ((unsigned)li < 64u && (unsigned)lj < 64u)
            v = g_topi[(b*4 + br)*LL + li*64 + lj];
        midx[e] = v;
    }
    if (t < 128){
        int br = t >> 5, j = t & 31;
        msc[t] = g_topv[(b*4 + br)*LL + i*64 + h*32 + j];
    }
    __syncthreads();

    const float* xp = &g_xpadR[(size_t)b*CC*LP];
    for (int e = t; e < 256*32; e += 256){
        int ci = e >> 5, j = e & 31;
        int br = ci >> 6, cch = ci & 63;
        int jj = h*32 + j;
        const float* xpc = xp + cch*LP;
        float sum = 0.f;
        #pragma unroll
        for (int kh = 0; kh < 3; kh++){
            int li = i + 1 - kh;
            if ((unsigned)li >= 64u) continue;
            int slot = 2 - kh;
            #pragma unroll
            for (int kw = 0; kw < 3; kw++){
                int lj = jj + 1 - kw;
                if ((unsigned)lj >= 64u) continue;
                int jo = lj - h*32 + 1;
                int m  = midx[br*102 + slot*34 + jo];
                int mi = m >> 6, mj = m & 63;
                sum += xpc[(mi + kh)*PW + mj + kw];
            }
        }
        Tc[e] = sum * msc[br*32 + j] * (1.0f/9.0f);
    }

    float a[4][2];
    #pragma unroll
    for (int ii = 0; ii < 4; ii++){ a[ii][0] = 0.f; a[ii][1] = 0.f; }
    for (int cc = 0; cc < 4; cc++){
        __syncthreads();
        for (int e = t; e < 4096; e += 256)
            wbuf[e] = wt1[(e >> 6)*256 + cc*64 + (e & 63)];
        __syncthreads();
        #pragma unroll 4
        for (int cil = 0; cil < 64; cil++){
            float2 v = *(const float2*)&Tc[(cc*64 + cil)*32 + j0];
            #pragma unroll
            for (int ii = 0; ii < 4; ii++){
                float wv = wbuf[(c0 + ii)*64 + cil];
                a[ii][0] += wv*v.x; a[ii][1] += wv*v.y;
            }
        }
    }
    #pragma unroll
    for (int ii = 0; ii < 4; ii++){
        float bv = __ldg(&bt1[c0 + ii]);
        *(float2*)&tex[(c0 + ii)*32 + j0] = make_float2(a[ii][0]+bv, a[ii][1]+bv);
    }
    __syncthreads();

    float* fx = Tc;
    for (int e = t; e < 64*32; e += 256){
        int cch = e >> 5, j = e & 31;
        fx[e]           = g_feature[((b*CC + cch)*HH + i)*WW + h*32 + j];
        fx[64*32 + e]   = x[((b*CC + cch)*HH + i)*WW + h*32 + j];
    }

    float a2[4][2];
    #pragma unroll
    for (int ii = 0; ii < 4; ii++){ a2[ii][0] = 0.f; a2[ii][1] = 0.f; }
    for (int cc = 0; cc < 3; cc++){
        __syncthreads();
        for (int e = t; e < 4096; e += 256)
            wbuf[e] = wt2[(e >> 6)*192 + cc*64 + (e & 63)];
        __syncthreads();
        const float* src = (cc == 2) ? tex : fx + cc*2048;
        #pragma unroll 4
        for (int cil = 0; cil < 64; cil++){
            float2 v = *(const float2*)&src[cil*32 + j0];
            #pragma unroll
            for (int ii = 0; ii < 4; ii++){
                float wv = wbuf[(c0 + ii)*64 + cil];
                a2[ii][0] += wv*v.x; a2[ii][1] += wv*v.y;
            }
        }
    }
    #pragma unroll
    for (int ii = 0; ii < 4; ii++){
        float bv = __ldg(&bt2[c0 + ii]);
        *(float2*)&out[((b*CC + c0 + ii)*HH + i)*WW + h*32 + j0] =
            make_float2(a2[ii][0]+bv, a2[ii][1]+bv);
    }
}

// ---------------- launch ----------------
extern "C" void kernel_launch(void* const* d_in, const int* in_sizes, int n_in,
                              void* d_out, int out_size){
    const float* x   = (const float*)d_in[0];
    const float* w1  = (const float*)d_in[1];
    const float* b1  = (const float*)d_in[2];
    const float* w2  = (const float*)d_in[3];
    const float* b2  = (const float*)d_in[4];
    const float* wt1 = (const float*)d_in[5];
    const float* bt1 = (const float*)d_in[6];
    const float* wt2 = (const float*)d_in[7];
    const float* bt2 = (const float*)d_in[8];
    float* out = (float*)d_out;

    const int CONV_SMEM = (13056 + 9216)*4;        // 89088
    const int GEMM_SMEM = 128*133*4;               // 68096
    const int STK_SMEM  = (2*BFLOATS + 128)*4;     // 38528
    const int FIN_SMEM  = (14464 + 408)*4;         // 59488

    static cudaStream_t sB = nullptr;
    static cudaEvent_t evFork = nullptr, evSim = nullptr, evJoin = nullptr;
    if (sB == nullptr){
        cudaStreamCreateWithFlags(&sB, cudaStreamNonBlocking);
        cudaEventCreateWithFlags(&evFork, cudaEventDisableTiming);
        cudaEventCreateWithFlags(&evSim,  cudaEventDisableTiming);
        cudaEventCreateWithFlags(&evJoin, cudaEventDisableTiming);
        cudaFuncSetAttribute(convg_kernel, cudaFuncAttributeMaxDynamicSharedMemorySize, CONV_SMEM);
        cudaFuncSetAttribute(gram_gemm,    cudaFuncAttributeMaxDynamicSharedMemorySize, GEMM_SMEM);
        cudaFuncSetAttribute(stopk_part,   cudaFuncAttributeMaxDynamicSharedMemorySize, STK_SMEM);
        cudaFuncSetAttribute(final_kernel, cudaFuncAttributeMaxDynamicSharedMemorySize, FIN_SMEM);
    }

    pad_kernel<<<dim3(66, 4), 256>>>(x);
    cudaEventRecord(evFork, 0);
    cudaStreamWaitEvent(sB, evFork, 0);

    // branch B: norms first (needed by stopk), then convs (needed by final)
    n2_kernel<<<dim3(18, 4), 256, 0, sB>>>();
    rn_kernel<<<dim3(64, 4), 64, 0, sB>>>();
    cudaEventRecord(evSim, sB);
    convg_kernel<<<dim3(64, 4), 256, CONV_SMEM, sB>>>(w1, b1, 0);
    convg_kernel<<<dim3(64, 4), 256, CONV_SMEM, sB>>>(w2, b2, 1);
    cudaEventRecord(evJoin, sB);

    // branch A (critical path): STRICT serial per-batch gram -> stopk, so each
    // stopk(b) reads G(b) while it is L2-resident and no concurrent gram write
    // thrashes the cache (round-10 failure mode removed).
    gram_gemm<<<630, 256, GEMM_SMEM>>>(0);
    cudaStreamWaitEvent(0, evSim, 0);          // rn ready before first stopk
    stopk_part<<<dim3(64, NSP), 256, STK_SMEM>>>(0);
    for (int b = 1; b < 4; b++){
        gram_gemm<<<630, 256, GEMM_SMEM>>>(b);
        stopk_part<<<dim3(64, NSP), 256, STK_SMEM>>>(b);
    }
    topk_merge<<<dim3(64, 4), 64>>>();

    cudaStreamWaitEvent(0, evJoin, 0);
    final_kernel<<<dim3(256, 2), 256, FIN_SMEM>>>(x, wt1, bt1, wt2, bt2, out);
}

// round 14
// speedup vs baseline: 1.1646x; 1.1646x over previous
#include <cuda_runtime.h>
#include <math.h>

#define BB 4
#define CC 64
#define HH 64
#define WW 64
#define LL 4096      // H*W
#define PW 66        // padded width/height
#define LP 4356      // 66*66 padded pixels

// ---------------- persistent device scratch ----------------
__device__ __align__(16) float g_xpadR[BB*CC*LP];     // reflect-padded x
__device__ __align__(16) float g_xpadZ[BB*CC*LP];     // zero-padded x (borders stay 0)
__device__ __align__(16) float g_reluZ[BB*CC*LP];     // zero-padded relu(conv1)
__device__ __align__(16) float g_G[(size_t)BB*LP*LP + 16]; // pixel gram
__device__ float g_n2[BB*LP];                         // per-pixel squared channel norms
__device__ float g_rn[BB*LL];                         // reciprocal patch norms
__device__ float g_feature[BB*CC*HH*WW];
__device__ float g_topv[BB*4*LL];
__device__ int   g_topi[BB*4*LL];
__device__ float g_pmv[BB*4*5*LL];                    // split-K partial top-5 values
__device__ int   g_pmi[BB*4*5*LL];                    // split-K partial top-5 indices

__device__ __forceinline__ int refl(int t){ return t < 0 ? -t : (t >= 64 ? 126 - t : t); }

// ---------------- K1: build reflect- and zero-padded inputs ----------------
__global__ void pad_kernel(const float* __restrict__ x){
    int b  = blockIdx.y;
    int pr = blockIdx.x;                 // 0..65
    int sr = refl(pr - 1);
    bool rin = (pr >= 1 && pr <= 64);
    for (int e = threadIdx.x; e < CC*PW; e += blockDim.x){
        int c = e / PW, pc = e % PW;
        int sc = refl(pc - 1);
        float v = x[((b*CC + c)*HH + sr)*WW + sc];
        g_xpadR[(b*CC + c)*LP + pr*PW + pc] = v;
        if (rin && pc >= 1 && pc <= 64)
            g_xpadZ[(b*CC + c)*LP + pr*PW + pc] = v;
    }
}

// ---------------- K2: 3x3 conv (zero pad), round-4 form ----------------
__global__ __launch_bounds__(256, 2) void convg_kernel(const float* __restrict__ w,
                                                       const float* __restrict__ bias,
                                                       int mode){
    extern __shared__ float cs[];
    float* s   = cs;            // [64][3][68]
    float* wsm = cs + 13056;    // [64co][16ci][9]
    int li = blockIdx.x, b = blockIdx.y;
    const float* in = (mode == 0) ? g_xpadZ : g_reluZ;
    const float* ib = in + (size_t)b*CC*LP;
    int t = threadIdx.x;

    for (int e = t; e < 64*3*33; e += 256){
        int ci = e / 99; int rem = e % 99; int r = rem / 33; int c2 = rem % 33;
        *(float2*)&s[(ci*3 + r)*68 + c2*2] =
            *(const float2*)&ib[(size_t)ci*LP + (li + r)*PW + c2*2];
    }

    int j0 = (t & 15)*4, c0 = (t >> 4)*4;
    float acc[4][4];
    #pragma unroll
    for (int i = 0; i < 4; i++)
        #pragma unroll
        for (int j = 0; j < 4; j++) acc[i][j] = 0.f;

    for (int cc = 0; cc < 4; cc++){
        __syncthreads();
        for (int e = t; e < 9216; e += 256)
            wsm[e] = w[(e / 144)*576 + cc*144 + (e % 144)];
        __syncthreads();
        #pragma unroll 2
        for (int cil = 0; cil < 16; cil++){
            const float* sr = &s[(cc*16 + cil)*3*68];
            float p[3][6];
            #pragma unroll
            for (int r = 0; r < 3; r++){
                float4 u = *(const float4*)&sr[r*68 + j0];
                float2 v = *(const float2*)&sr[r*68 + j0 + 4];
                p[r][0]=u.x; p[r][1]=u.y; p[r][2]=u.z; p[r][3]=u.w; p[r][4]=v.x; p[r][5]=v.y;
            }
            #pragma unroll
            for (int i = 0; i < 4; i++){
                const float* wp = &wsm[(c0 + i)*144 + cil*9];
                float w0=wp[0],w1=wp[1],w2=wp[2],w3=wp[3],w4=wp[4],
                      w5=wp[5],w6=wp[6],w7=wp[7],w8=wp[8];
                #pragma unroll
                for (int j = 0; j < 4; j++)
                    acc[i][j] += p[0][j]*w0 + p[0][j+1]*w1 + p[0][j+2]*w2
                               + p[1][j]*w3 + p[1][j+1]*w4 + p[1][j+2]*w5
                               + p[2][j]*w6 + p[2][j+1]*w7 + p[2][j+2]*w8;
            }
        }
    }

    float bv[4];
    #pragma unroll
    for (int i = 0; i < 4; i++) bv[i] = __ldg(&bias[c0 + i]);
    if (mode == 0){
        #pragma unroll
        for (int i = 0; i < 4; i++)
            #pragma unroll
            for (int j = 0; j < 4; j++)
                g_reluZ[(size_t)(b*CC + c0 + i)*LP + (li + 1)*PW + (j0 + j + 1)] =
                    fmaxf(acc[i][j] + bv[i], 0.f);
    } else {
        #pragma unroll
        for (int i = 0; i < 4; i++){
            float4 o = make_float4(acc[i][0]+bv[i], acc[i][1]+bv[i],
                                   acc[i][2]+bv[i], acc[i][3]+bv[i]);
            *(float4*)&g_feature[((b*CC + c0 + i)*HH + li)*WW + j0] = o;
        }
    }
}

// ---------------- K3: pixel gram GEMM, symmetric-halved (round-6 form) ----------------
__global__ __launch_bounds__(256, 2) void gram_gemm(){
    extern __shared__ float sg[];
    float* Qs    = sg;            // [64][128]
    float* Ks    = sg + 8192;     // [64][128]
    float* stage = sg;            // alias: [128][133]
    int sIdx = blockIdx.x, b = blockIdx.y;
    int qt = (int)((sqrtf(8.f*sIdx + 1.f) - 1.f)*0.5f);
    while ((qt + 1)*(qt + 2)/2 <= sIdx) qt++;
    while (qt*(qt + 1)/2 > sIdx) qt--;
    int pt = sIdx - qt*(qt + 1)/2;
    int p0 = pt*128, q0 = qt*128;
    int t = threadIdx.x, ty = t >> 4, tx = t & 15;
    const float* xp = &g_xpadR[(size_t)b*CC*LP];

    for (int e = t; e < 64*128; e += 256){
        int d = e >> 7, col = e & 127;
        int p = p0 + col, q = q0 + col;
        Qs[e] = (p < LP) ? xp[(size_t)d*LP + p] : 0.f;
        Ks[e] = (q < LP) ? xp[(size_t)d*LP + q] : 0.f;
    }
    __syncthreads();

    float acc[8][8];
    #pragma unroll
    for (int i = 0; i < 8; i++)
        #pragma unroll
        for (int j = 0; j < 8; j++) acc[i][j] = 0.f;

    #pragma unroll 4
    for (int d = 0; d < 64; d++){
        float4 a0 = *(const float4*)&Qs[d*128 + ty*4];
        float4 a1 = *(const float4*)&Qs[d*128 + 64 + ty*4];
        float4 b0 = *(const float4*)&Ks[d*128 + tx*4];
        float4 b1 = *(const float4*)&Ks[d*128 + 64 + tx*4];
        float ar[8] = {a0.x,a0.y,a0.z,a0.w,a1.x,a1.y,a1.z,a1.w};
        float br[8] = {b0.x,b0.y,b0.z,b0.w,b1.x,b1.y,b1.z,b1.w};
        #pragma unroll
        for (int i = 0; i < 8; i++)
            #pragma unroll
            for (int j = 0; j < 8; j++) acc[i][j] += ar[i]*br[j];
    }

    float* Gb = &g_G[(size_t)b*LP*LP];
    #pragma unroll
    for (int i = 0; i < 8; i++){
        int p = p0 + ((i < 4) ? (ty*4 + i) : (64 + ty*4 + i - 4));
        if (p >= LP) continue;
        #pragma unroll
        for (int half = 0; half < 2; half++){
            int q = q0 + half*64 + tx*4;
            if (q + 4 <= LP){
                float4 v = make_float4(acc[i][half*4], acc[i][half*4+1],
                                       acc[i][half*4+2], acc[i][half*4+3]);
                *(float4*)&Gb[(size_t)p*LP + q] = v;
            } else {
                for (int j = 0; j < 4; j++)
                    if (q + j < LP) Gb[(size_t)p*LP + q + j] = acc[i][half*4 + j];
            }
        }
    }

    if (pt != qt){
        __syncthreads();
        #pragma unroll
        for (int i = 0; i < 8; i++){
            int pl = (i < 4) ? (ty*4 + i) : (64 + ty*4 + i - 4);
            #pragma unroll
            for (int j = 0; j < 8; j++){
                int ql = (j < 4) ? (tx*4 + j) : (64 + tx*4 + j - 4);
                stage[pl*133 + ql] = acc[i][j];
            }
        }
        __syncthreads();
        int wid = t >> 5, lane = t & 31;
        for (int r = wid; r < 128; r += 8){
            int q = q0 + r;
            if (q < LP){
                float4 o;
                o.x = stage[(lane*4 + 0)*133 + r];
                o.y = stage[(lane*4 + 1)*133 + r];
                o.z = stage[(lane*4 + 2)*133 + r];
                o.w = stage[(lane*4 + 3)*133 + r];
                *(float4*)&Gb[(size_t)q*LP + p0 + lane*4] = o;
            }
        }
    }
}

// ---------------- K4a: per-pixel squared channel norms ----------------
__global__ void n2_kernel(){
    int b = blockIdx.y;
    int p = blockIdx.x*256 + threadIdx.x;
    if (p >= LP) return;
    const float* xp = g_xpadR + (size_t)b*CC*LP + p;
    float s = 0.f;
    #pragma unroll 8
    for (int c = 0; c < CC; c++){ float v = xp[(size_t)c*LP]; s += v*v; }
    g_n2[b*LP + p] = s;
}

// ---------------- K4b: reciprocal patch norms ----------------
__global__ void rn_kernel(){
    int b = blockIdx.y, li = blockIdx.x, lj = threadIdx.x;   // 64 threads
    float s = 0.f;
    #pragma unroll
    for (int kh = 0; kh < 3; kh++)
        #pragma unroll
        for (int kw = 0; kw < 3; kw++)
            s += g_n2[b*LP + (li + kh)*PW + lj + kw];
    g_rn[b*LL + li*64 + lj] = 1.0f / fmaxf(sqrtf(s), 1e-12f);
}

// ---------------- K5a: split-K top-5 (round-6 form, L2-friendly grid order) --------
// Grid = (sp, b*64+li): the 4 sp-blocks sharing the SAME 198 G rows are now
// consecutive -> co-scheduled in one wave -> rows fetched from DRAM once and
// served from L2 for the other 3 (plus 2/3 row overlap with neighboring li).
__global__ __launch_bounds__(256, 3) void stopk_part(){
    extern __shared__ float sm[];
    float* Bs  = sm;                 // [3][66][68] = 13464 floats
    float* rnq = sm + 13464;         // [64]
    float* rnk = rnq + 64;           // [64]
    float* Sc  = sm;                 // alias

    int b  = blockIdx.y >> 6;
    int li = blockIdx.y & 63;
    int sp = blockIdx.x;             // 0..3
    int t  = threadIdx.x, ty = t >> 4, tx = t & 15;
    int tr = t >> 5, tc2 = t & 31;
    int qq = t & 63, seg = t >> 6;

    if (t < 64) rnq[t] = g_rn[b*LL + li*64 + t];

    float tv[5]; int tix[5];
    #pragma unroll
    for (int i = 0; i < 5; i++){ tv[i] = -1e30f; tix[i] = 0; }

    const float* growbase = &g_G[(size_t)b*LP*LP] + (size_t)(li*PW)*LP;

    for (int mi = sp*16; mi < sp*16 + 16; mi++){
        __syncthreads();
        if (t < 64) rnk[t] = g_rn[b*LL + mi*64 + t];
        #pragma unroll
        for (int pass = 0; pass < 25; pass++){
            int row = pass*8 + tr;
            if (row < 198){
                int kh = (row >= 132) ? 2 : ((row >= 66) ? 1 : 0);
                const float2 v = *(const float2*)(growbase + (size_t)row*LP + (mi + kh)*PW + tc2*2);
                *(float2*)&Bs[row*68 + tc2*2] = v;
            }
        }
        if (t < 198){
            int row = t;
            int kh = (row >= 132) ? 2 : ((row >= 66) ? 1 : 0);
            const float2 v = *(const float2*)(growbase + (size_t)row*LP + (mi + kh)*PW + 64);
            *(float2*)&Bs[row*68 + 64] = v;
        }
        __syncthreads();

        int lj0 = ty*4, mj0 = tx*4;
        float S[4][4];
        #pragma unroll
        for (int i = 0; i < 4; i++)
            #pragma unroll
            for (int j = 0; j < 4; j++) S[i][j] = 0.f;

        #pragma unroll
        for (int kh = 0; kh < 3; kh++){
            float wv[6][6];
            #pragma unroll
            for (int r = 0; r < 6; r++){
                float4 u = *(const float4*)&Bs[(kh*66 + lj0 + r)*68 + mj0];
                float2 v = *(const float2*)&Bs[(kh*66 + lj0 + r)*68 + mj0 + 4];
                wv[r][0]=u.x; wv[r][1]=u.y; wv[r][2]=u.z; wv[r][3]=u.w; wv[r][4]=v.x; wv[r][5]=v.y;
            }
            #pragma unroll
            for (int kw = 0; kw < 3; kw++)
                #pragma unroll
                for (int i = 0; i < 4; i++)
                    #pragma unroll
                    for (int j = 0; j < 4; j++)
                        S[i][j] += wv[i+kw][j+kw];
        }
        __syncthreads();

        #pragma unroll
        for (int i = 0; i < 4; i++){
            float rq = rnq[lj0 + i];
            #pragma unroll
            for (int j = 0; j < 4; j++)
                Sc[(lj0 + i)*65 + mj0 + j] = S[i][j] * rq * rnk[mj0 + j];
        }
        __syncthreads();

        {   // all 256 threads: query qq, keys [seg*16, seg*16+16)
            const float* rowp = &Sc[qq*65 + seg*16];
            int k0 = (mi << 6) + seg*16;
            for (int jj = 0; jj < 16; jj++){
                float s = rowp[jj];
                if (s > tv[4]){
                    float v0 = s; int i0 = k0 + jj;
                    #pragma unroll
                    for (int p = 0; p < 5; p++){
                        if (v0 > tv[p]){
                            float tpv = tv[p]; int tpi = tix[p];
                            tv[p] = v0; tix[p] = i0;
                            v0 = tpv; i0 = tpi;
                        }
                    }
                }
            }
        }
    }

    // merge 4 segment lists per query (exact value-desc, index-asc), store top-5
    __syncthreads();
    float* mv = sm;                   // [64][20]
    int*   mx = (int*)(sm + 1280);    // [64][20]
    #pragma unroll
    for (int r = 0; r < 5; r++){
        mv[qq*20 + seg*5 + r] = tv[r];
        mx[qq*20 + seg*5 + r] = tix[r];
    }
    __syncthreads();
    if (t < 64){
        unsigned used = 0;
        int l = li*64 + t;
        for (int r = 0; r < 5; r++){
            float bvv = -3e38f; int bii = 0x7fffffff; int bc = 0;
            #pragma unroll
            for (int c = 0; c < 20; c++){
                if (used & (1u << c)) continue;
                float v = mv[t*20 + c]; int ii = mx[t*20 + c];
                if (v > bvv || (v == bvv && ii < bii)){ bvv = v; bii = ii; bc = c; }
            }
            used |= 1u << bc;
            g_pmv[((b*4 + sp)*5 + r)*LL + l] = bvv;
            g_pmi[((b*4 + sp)*5 + r)*LL + l] = bii;
        }
    }
}

// ---------------- K5b: merge 4 split lists into final ranks 1..4 ----------------
__global__ void topk_merge(){
    int b = blockIdx.y, li = blockIdx.x, q = threadIdx.x;  // 64 threads
    int l = li*64 + q;
    float mv[20]; int mx[20];
    #pragma unroll
    for (int sp = 0; sp < 4; sp++)
        #pragma unroll
        for (int r = 0; r < 5; r++){
            mv[sp*5 + r] = g_pmv[((b*4 + sp)*5 + r)*LL + l];
            mx[sp*5 + r] = g_pmi[((b*4 + sp)*5 + r)*LL + l];
        }
    unsigned used = 0;
    for (int r = 0; r < 5; r++){
        float bvv = -3e38f; int bii = 0x7fffffff; int bc = 0;
        #pragma unroll
        for (int c = 0; c < 20; c++){
            if (used & (1u << c)) continue;
            if (mv[c] > bvv || (mv[c] == bvv && mx[c] < bii)){ bvv = mv[c]; bii = mx[c]; bc = c; }
        }
        used |= 1u << bc;
        if (r >= 1){
            g_topv[(b*4 + (r-1))*LL + l] = bvv;
            g_topi[(b*4 + (r-1))*LL + l] = bii;
        }
    }
}

// ---------------- K6: gather+fold texture, 1x1 convs, pixel-split x2 ----------------
__global__ __launch_bounds__(256, 3) void final_kernel(const float* __restrict__ x,
                             const float* __restrict__ wt1, const float* __restrict__ bt1,
                             const float* __restrict__ wt2, const float* __restrict__ bt2,
                             float* __restrict__ out){
    extern __shared__ float sm[];
    float* Tc   = sm;                    // [256][32]
    float* tex  = sm + 8192;             // [64][32]
    float* wbuf = sm + 10240;            // [64][64]
    float* msc  = sm + 14336;            // [4][32]
    int*   midx = (int*)(sm + 14464);    // [4][3][34]
    int b = blockIdx.x >> 6, i = blockIdx.x & 63;
    int h = blockIdx.y;
    int t = threadIdx.x;
    int j0 = (t & 15)*2, c0 = (t >> 4)*4;

    for (int e = t; e < 4*3*34; e += 256){
        int br = e / 102, rr = (e / 34) % 3, jo = e % 34;
        int li = i - 1 + rr, lj = h*32 - 1 + jo;
        int v = 0;
        if ((unsigned)li < 64u && (unsigned)lj < 64u)
            v = g_topi[(b*4 + br)*LL + li*64 + lj];
        midx[e] = v;
    }
    if (t < 128){
        int br = t >> 5, j = t & 31;
        msc[t] = g_topv[(b*4 + br)*LL + i*64 + h*32 + j];
    }
    __syncthreads();

    const float* xp = &g_xpadR[(size_t)b*CC*LP];
    for (int e = t; e < 256*32; e += 256){
        int ci = e >> 5, j = e & 31;
        int br = ci >> 6, cch = ci & 63;
        int jj = h*32 + j;
        const float* xpc = xp + cch*LP;
        float sum = 0.f;
        #pragma unroll
        for (int kh = 0; kh < 3; kh++){
            int li = i + 1 - kh;
            if ((unsigned)li >= 64u) continue;
            int slot = 2 - kh;
            #pragma unroll
            for (int kw = 0; kw < 3; kw++){
                int lj = jj + 1 - kw;
                if ((unsigned)lj >= 64u) continue;
                int jo = lj - h*32 + 1;
                int m  = midx[br*102 + slot*34 + jo];
                int mi = m >> 6, mj = m & 63;
                sum += xpc[(mi + kh)*PW + mj + kw];
            }
        }
        Tc[e] = sum * msc[br*32 + j] * (1.0f/9.0f);
    }

    float a[4][2];
    #pragma unroll
    for (int ii = 0; ii < 4; ii++){ a[ii][0] = 0.f; a[ii][1] = 0.f; }
    for (int cc = 0; cc < 4; cc++){
        __syncthreads();
        for (int e = t; e < 4096; e += 256)
            wbuf[e] = wt1[(e >> 6)*256 + cc*64 + (e & 63)];
        __syncthreads();
        #pragma unroll 4
        for (int cil = 0; cil < 64; cil++){
            float2 v = *(const float2*)&Tc[(cc*64 + cil)*32 + j0];
            #pragma unroll
            for (int ii = 0; ii < 4; ii++){
                float wv = wbuf[(c0 + ii)*64 + cil];
                a[ii][0] += wv*v.x; a[ii][1] += wv*v.y;
            }
        }
    }
    #pragma unroll
    for (int ii = 0; ii < 4; ii++){
        float bv = __ldg(&bt1[c0 + ii]);
        *(float2*)&tex[(c0 + ii)*32 + j0] = make_float2(a[ii][0]+bv, a[ii][1]+bv);
    }
    __syncthreads();

    float* fx = Tc;
    for (int e = t; e < 64*32; e += 256){
        int cch = e >> 5, j = e & 31;
        fx[e]           = g_feature[((b*CC + cch)*HH + i)*WW + h*32 + j];
        fx[64*32 + e]   = x[((b*CC + cch)*HH + i)*WW + h*32 + j];
    }

    float a2[4][2];
    #pragma unroll
    for (int ii = 0; ii < 4; ii++){ a2[ii][0] = 0.f; a2[ii][1] = 0.f; }
    for (int cc = 0; cc < 3; cc++){
        __syncthreads();
        for (int e = t; e < 4096; e += 256)
            wbuf[e] = wt2[(e >> 6)*192 + cc*64 + (e & 63)];
        __syncthreads();
        const float* src = (cc == 2) ? tex : fx + cc*2048;
        #pragma unroll 4
        for (int cil = 0; cil < 64; cil++){
            float2 v = *(const float2*)&src[cil*32 + j0];
            #pragma unroll
            for (int ii = 0; ii < 4; ii++){
                float wv = wbuf[(c0 + ii)*64 + cil];
                a2[ii][0] += wv*v.x; a2[ii][1] += wv*v.y;
            }
        }
    }
    #pragma unroll
    for (int ii = 0; ii < 4; ii++){
        float bv = __ldg(&bt2[c0 + ii]);
        *(float2*)&out[((b*CC + c0 + ii)*HH + i)*WW + h*32 + j0] =
            make_float2(a2[ii][0]+bv, a2[ii][1]+bv);
    }
}

// ---------------- launch ----------------
extern "C" void kernel_launch(void* const* d_in, const int* in_sizes, int n_in,
                              void* d_out, int out_size){
    const float* x   = (const float*)d_in[0];
    const float* w1  = (const float*)d_in[1];
    const float* b1  = (const float*)d_in[2];
    const float* w2  = (const float*)d_in[3];
    const float* b2  = (const float*)d_in[4];
    const float* wt1 = (const float*)d_in[5];
    const float* bt1 = (const float*)d_in[6];
    const float* wt2 = (const float*)d_in[7];
    const float* bt2 = (const float*)d_in[8];
    float* out = (float*)d_out;

    const int CONV_SMEM = (13056 + 9216)*4;        // 89088
    const int GEMM_SMEM = 128*133*4;               // 68096
    const int STK_SMEM  = (13464 + 128)*4;         // 54368
    const int FIN_SMEM  = (14464 + 408)*4;         // 59488

    static cudaStream_t sB = nullptr;
    static cudaEvent_t evFork = nullptr, evSim = nullptr, evJoin = nullptr;
    if (sB == nullptr){
        cudaStreamCreateWithFlags(&sB, cudaStreamNonBlocking);
        cudaEventCreateWithFlags(&evFork, cudaEventDisableTiming);
        cudaEventCreateWithFlags(&evSim,  cudaEventDisableTiming);
        cudaEventCreateWithFlags(&evJoin, cudaEventDisableTiming);
        cudaFuncSetAttribute(convg_kernel, cudaFuncAttributeMaxDynamicSharedMemorySize, CONV_SMEM);
        cudaFuncSetAttribute(gram_gemm,    cudaFuncAttributeMaxDynamicSharedMemorySize, GEMM_SMEM);
        cudaFuncSetAttribute(stopk_part,   cudaFuncAttributeMaxDynamicSharedMemorySize, STK_SMEM);
        cudaFuncSetAttribute(final_kernel, cudaFuncAttributeMaxDynamicSharedMemorySize, FIN_SMEM);
    }

    // submission order arranged so stopk_part is the 6th node (ncu -s 5 -c 1)
    pad_kernel<<<dim3(66, 4), 256>>>(x);                              // 1
    cudaEventRecord(evFork, 0);
    cudaStreamWaitEvent(sB, evFork, 0);

    n2_kernel<<<dim3(18, 4), 256, 0, sB>>>();                         // 2
    rn_kernel<<<dim3(64, 4), 64, 0, sB>>>();                          // 3
    cudaEventRecord(evSim, sB);

    gram_gemm<<<dim3(630, 4), 256, GEMM_SMEM>>>();                    // 4
    convg_kernel<<<dim3(64, 4), 256, CONV_SMEM, sB>>>(w1, b1, 0);     // 5

    cudaStreamWaitEvent(0, evSim, 0);
    stopk_part<<<dim3(4, 256), 256, STK_SMEM>>>();                    // 6  <- profiled

    convg_kernel<<<dim3(64, 4), 256, CONV_SMEM, sB>>>(w2, b2, 1);     // 7
    cudaEventRecord(evJoin, sB);

    topk_merge<<<dim3(64, 4), 64>>>();                                // 8

    cudaStreamWaitEvent(0, evJoin, 0);
    final_kernel<<<dim3(256, 2), 256, FIN_SMEM>>>(x, wt1, bt1, wt2, bt2, out);  // 9
}

// round 15
// speedup vs baseline: 1.2838x; 1.1023x over previous
#include <cuda_runtime.h>
#include <math.h>

#define BB 4
#define CC 64
#define HH 64
#define WW 64
#define LL 4096      // H*W
#define PW 66        // padded width/height
#define LP 4356      // 66*66 padded pixels

// ---------------- persistent device scratch ----------------
__device__ __align__(16) float g_xpadR[BB*CC*LP];     // reflect-padded x (channel-major)
__device__ __align__(16) float g_xpadT[(size_t)BB*LP*CC]; // reflect-padded x (channels-last)
__device__ __align__(16) float g_xpadZ[BB*CC*LP];     // zero-padded x (borders stay 0)
__device__ __align__(16) float g_reluZ[BB*CC*LP];     // zero-padded relu(conv1)
__device__ __align__(16) float g_G[(size_t)BB*LP*LP + 16]; // pixel gram
__device__ float g_n2[BB*LP];                         // per-pixel squared channel norms
__device__ float g_rn[BB*LL];                         // reciprocal patch norms
__device__ float g_feature[BB*CC*HH*WW];
__device__ float g_topv[BB*4*LL];
__device__ int   g_topi[BB*4*LL];
__device__ float g_pmv[BB*4*5*LL];                    // split-K partial top-5 values
__device__ int   g_pmi[BB*4*5*LL];                    // split-K partial top-5 indices

__device__ __forceinline__ int refl(int t){ return t < 0 ? -t : (t >= 64 ? 126 - t : t); }

// ---------------- K1: build reflect- and zero-padded inputs ----------------
__global__ void pad_kernel(const float* __restrict__ x){
    int b  = blockIdx.y;
    int pr = blockIdx.x;                 // 0..65
    int sr = refl(pr - 1);
    bool rin = (pr >= 1 && pr <= 64);
    for (int e = threadIdx.x; e < CC*PW; e += blockDim.x){
        int c = e / PW, pc = e % PW;
        int sc = refl(pc - 1);
        float v = x[((b*CC + c)*HH + sr)*WW + sc];
        g_xpadR[(b*CC + c)*LP + pr*PW + pc] = v;
        if (rin && pc >= 1 && pc <= 64)
            g_xpadZ[(b*CC + c)*LP + pr*PW + pc] = v;
    }
}

// ---------------- K1b: channels-last transpose of xpadR ----------------
__global__ void xt_kernel(){
    __shared__ float s[64*65];
    int b  = blockIdx.y;
    int p0 = blockIdx.x*64;
    int t  = threadIdx.x;
    for (int e = t; e < 64*64; e += 256){
        int c = e >> 6, dp = e & 63;
        int p = p0 + dp;
        s[c*65 + dp] = (p < LP) ? g_xpadR[(b*CC + c)*LP + p] : 0.f;
    }
    __syncthreads();
    for (int e = t; e < 64*64; e += 256){
        int dp = e >> 6, c = e & 63;
        int p = p0 + dp;
        if (p < LP) g_xpadT[((size_t)b*LP + p)*CC + c] = s[c*65 + dp];
    }
}

// ---------------- K2: 3x3 conv (zero pad), round-4 form ----------------
__global__ __launch_bounds__(256, 2) void convg_kernel(const float* __restrict__ w,
                                                       const float* __restrict__ bias,
                                                       int mode){
    extern __shared__ float cs[];
    float* s   = cs;            // [64][3][68]
    float* wsm = cs + 13056;    // [64co][16ci][9]
    int li = blockIdx.x, b = blockIdx.y;
    const float* in = (mode == 0) ? g_xpadZ : g_reluZ;
    const float* ib = in + (size_t)b*CC*LP;
    int t = threadIdx.x;

    for (int e = t; e < 64*3*33; e += 256){
        int ci = e / 99; int rem = e % 99; int r = rem / 33; int c2 = rem % 33;
        *(float2*)&s[(ci*3 + r)*68 + c2*2] =
            *(const float2*)&ib[(size_t)ci*LP + (li + r)*PW + c2*2];
    }

    int j0 = (t & 15)*4, c0 = (t >> 4)*4;
    float acc[4][4];
    #pragma unroll
    for (int i = 0; i < 4; i++)
        #pragma unroll
        for (int j = 0; j < 4; j++) acc[i][j] = 0.f;

    for (int cc = 0; cc < 4; cc++){
        __syncthreads();
        for (int e = t; e < 9216; e += 256)
            wsm[e] = w[(e / 144)*576 + cc*144 + (e % 144)];
        __syncthreads();
        #pragma unroll 2
        for (int cil = 0; cil < 16; cil++){
            const float* sr = &s[(cc*16 + cil)*3*68];
            float p[3][6];
            #pragma unroll
            for (int r = 0; r < 3; r++){
                float4 u = *(const float4*)&sr[r*68 + j0];
                float2 v = *(const float2*)&sr[r*68 + j0 + 4];
                p[r][0]=u.x; p[r][1]=u.y; p[r][2]=u.z; p[r][3]=u.w; p[r][4]=v.x; p[r][5]=v.y;
            }
            #pragma unroll
            for (int i = 0; i < 4; i++){
                const float* wp = &wsm[(c0 + i)*144 + cil*9];
                float w0=wp[0],w1=wp[1],w2=wp[2],w3=wp[3],w4=wp[4],
                      w5=wp[5],w6=wp[6],w7=wp[7],w8=wp[8];
                #pragma unroll
                for (int j = 0; j < 4; j++)
                    acc[i][j] += p[0][j]*w0 + p[0][j+1]*w1 + p[0][j+2]*w2
                               + p[1][j]*w3 + p[1][j+1]*w4 + p[1][j+2]*w5
                               + p[2][j]*w6 + p[2][j+1]*w7 + p[2][j+2]*w8;
            }
        }
    }

    float bv[4];
    #pragma unroll
    for (int i = 0; i < 4; i++) bv[i] = __ldg(&bias[c0 + i]);
    if (mode == 0){
        #pragma unroll
        for (int i = 0; i < 4; i++)
            #pragma unroll
            for (int j = 0; j < 4; j++)
                g_reluZ[(size_t)(b*CC + c0 + i)*LP + (li + 1)*PW + (j0 + j + 1)] =
                    fmaxf(acc[i][j] + bv[i], 0.f);
    } else {
        #pragma unroll
        for (int i = 0; i < 4; i++){
            float4 o = make_float4(acc[i][0]+bv[i], acc[i][1]+bv[i],
                                   acc[i][2]+bv[i], acc[i][3]+bv[i]);
            *(float4*)&g_feature[((b*CC + c0 + i)*HH + li)*WW + j0] = o;
        }
    }
}

// ---------------- K3: pixel gram GEMM, symmetric-halved (round-6 form) ----------------
__global__ __launch_bounds__(256, 2) void gram_gemm(){
    extern __shared__ float sg[];
    float* Qs    = sg;            // [64][128]
    float* Ks    = sg + 8192;     // [64][128]
    float* stage = sg;            // alias: [128][133]
    int sIdx = blockIdx.x, b = blockIdx.y;
    int qt = (int)((sqrtf(8.f*sIdx + 1.f) - 1.f)*0.5f);
    while ((qt + 1)*(qt + 2)/2 <= sIdx) qt++;
    while (qt*(qt + 1)/2 > sIdx) qt--;
    int pt = sIdx - qt*(qt + 1)/2;
    int p0 = pt*128, q0 = qt*128;
    int t = threadIdx.x, ty = t >> 4, tx = t & 15;
    const float* xp = &g_xpadR[(size_t)b*CC*LP];

    for (int e = t; e < 64*128; e += 256){
        int d = e >> 7, col = e & 127;
        int p = p0 + col, q = q0 + col;
        Qs[e] = (p < LP) ? xp[(size_t)d*LP + p] : 0.f;
        Ks[e] = (q < LP) ? xp[(size_t)d*LP + q] : 0.f;
    }
    __syncthreads();

    float acc[8][8];
    #pragma unroll
    for (int i = 0; i < 8; i++)
        #pragma unroll
        for (int j = 0; j < 8; j++) acc[i][j] = 0.f;

    #pragma unroll 4
    for (int d = 0; d < 64; d++){
        float4 a0 = *(const float4*)&Qs[d*128 + ty*4];
        float4 a1 = *(const float4*)&Qs[d*128 + 64 + ty*4];
        float4 b0 = *(const float4*)&Ks[d*128 + tx*4];
        float4 b1 = *(const float4*)&Ks[d*128 + 64 + tx*4];
        float ar[8] = {a0.x,a0.y,a0.z,a0.w,a1.x,a1.y,a1.z,a1.w};
        float br[8] = {b0.x,b0.y,b0.z,b0.w,b1.x,b1.y,b1.z,b1.w};
        #pragma unroll
        for (int i = 0; i < 8; i++)
            #pragma unroll
            for (int j = 0; j < 8; j++) acc[i][j] += ar[i]*br[j];
    }

    float* Gb = &g_G[(size_t)b*LP*LP];
    #pragma unroll
    for (int i = 0; i < 8; i++){
        int p = p0 + ((i < 4) ? (ty*4 + i) : (64 + ty*4 + i - 4));
        if (p >= LP) continue;
        #pragma unroll
        for (int half = 0; half < 2; half++){
            int q = q0 + half*64 + tx*4;
            if (q + 4 <= LP){
                float4 v = make_float4(acc[i][half*4], acc[i][half*4+1],
                                       acc[i][half*4+2], acc[i][half*4+3]);
                *(float4*)&Gb[(size_t)p*LP + q] = v;
            } else {
                for (int j = 0; j < 4; j++)
                    if (q + j < LP) Gb[(size_t)p*LP + q + j] = acc[i][half*4 + j];
            }
        }
    }

    if (pt != qt){
        __syncthreads();
        #pragma unroll
        for (int i = 0; i < 8; i++){
            int pl = (i < 4) ? (ty*4 + i) : (64 + ty*4 + i - 4);
            #pragma unroll
            for (int j = 0; j < 8; j++){
                int ql = (j < 4) ? (tx*4 + j) : (64 + tx*4 + j - 4);
                stage[pl*133 + ql] = acc[i][j];
            }
        }
        __syncthreads();
        int wid = t >> 5, lane = t & 31;
        for (int r = wid; r < 128; r += 8){
            int q = q0 + r;
            if (q < LP){
                float4 o;
                o.x = stage[(lane*4 + 0)*133 + r];
                o.y = stage[(lane*4 + 1)*133 + r];
                o.z = stage[(lane*4 + 2)*133 + r];
                o.w = stage[(lane*4 + 3)*133 + r];
                *(float4*)&Gb[(size_t)q*LP + p0 + lane*4] = o;
            }
        }
    }
}

// ---------------- K4a: per-pixel squared channel norms ----------------
__global__ void n2_kernel(){
    int b = blockIdx.y;
    int p = blockIdx.x*256 + threadIdx.x;
    if (p >= LP) return;
    const float* xp = g_xpadR + (size_t)b*CC*LP + p;
    float s = 0.f;
    #pragma unroll 8
    for (int c = 0; c < CC; c++){ float v = xp[(size_t)c*LP]; s += v*v; }
    g_n2[b*LP + p] = s;
}

// ---------------- K4b: reciprocal patch norms ----------------
__global__ void rn_kernel(){
    int b = blockIdx.y, li = blockIdx.x, lj = threadIdx.x;   // 64 threads
    float s = 0.f;
    #pragma unroll
    for (int kh = 0; kh < 3; kh++)
        #pragma unroll
        for (int kw = 0; kw < 3; kw++)
            s += g_n2[b*LP + (li + kh)*PW + lj + kw];
    g_rn[b*LL + li*64 + lj] = 1.0f / fmaxf(sqrtf(s), 1e-12f);
}

// ---------------- K5a: split-K top-5 (round-14 champion form) ----------------
__global__ __launch_bounds__(256, 3) void stopk_part(){
    extern __shared__ float sm[];
    float* Bs  = sm;                 // [3][66][68] = 13464 floats
    float* rnq = sm + 13464;         // [64]
    float* rnk = rnq + 64;           // [64]
    float* Sc  = sm;                 // alias

    int b  = blockIdx.y >> 6;
    int li = blockIdx.y & 63;
    int sp = blockIdx.x;             // 0..3
    int t  = threadIdx.x, ty = t >> 4, tx = t & 15;
    int tr = t >> 5, tc2 = t & 31;
    int qq = t & 63, seg = t >> 6;

    if (t < 64) rnq[t] = g_rn[b*LL + li*64 + t];

    float tv[5]; int tix[5];
    #pragma unroll
    for (int i = 0; i < 5; i++){ tv[i] = -1e30f; tix[i] = 0; }

    const float* growbase = &g_G[(size_t)b*LP*LP] + (size_t)(li*PW)*LP;

    for (int mi = sp*16; mi < sp*16 + 16; mi++){
        __syncthreads();
        if (t < 64) rnk[t] = g_rn[b*LL + mi*64 + t];
        #pragma unroll
        for (int pass = 0; pass < 25; pass++){
            int row = pass*8 + tr;
            if (row < 198){
                int kh = (row >= 132) ? 2 : ((row >= 66) ? 1 : 0);
                const float2 v = *(const float2*)(growbase + (size_t)row*LP + (mi + kh)*PW + tc2*2);
                *(float2*)&Bs[row*68 + tc2*2] = v;
            }
        }
        if (t < 198){
            int row = t;
            int kh = (row >= 132) ? 2 : ((row >= 66) ? 1 : 0);
            const float2 v = *(const float2*)(growbase + (size_t)row*LP + (mi + kh)*PW + 64);
            *(float2*)&Bs[row*68 + 64] = v;
        }
        __syncthreads();

        int lj0 = ty*4, mj0 = tx*4;
        float S[4][4];
        #pragma unroll
        for (int i = 0; i < 4; i++)
            #pragma unroll
            for (int j = 0; j < 4; j++) S[i][j] = 0.f;

        #pragma unroll
        for (int kh = 0; kh < 3; kh++){
            float wv[6][6];
            #pragma unroll
            for (int r = 0; r < 6; r++){
                float4 u = *(const float4*)&Bs[(kh*66 + lj0 + r)*68 + mj0];
                float2 v = *(const float2*)&Bs[(kh*66 + lj0 + r)*68 + mj0 + 4];
                wv[r][0]=u.x; wv[r][1]=u.y; wv[r][2]=u.z; wv[r][3]=u.w; wv[r][4]=v.x; wv[r][5]=v.y;
            }
            #pragma unroll
            for (int kw = 0; kw < 3; kw++)
                #pragma unroll
                for (int i = 0; i < 4; i++)
                    #pragma unroll
                    for (int j = 0; j < 4; j++)
                        S[i][j] += wv[i+kw][j+kw];
        }
        __syncthreads();

        #pragma unroll
        for (int i = 0; i < 4; i++){
            float rq = rnq[lj0 + i];
            #pragma unroll
            for (int j = 0; j < 4; j++)
                Sc[(lj0 + i)*65 + mj0 + j] = S[i][j] * rq * rnk[mj0 + j];
        }
        __syncthreads();

        {
            const float* rowp = &Sc[qq*65 + seg*16];
            int k0 = (mi << 6) + seg*16;
            for (int jj = 0; jj < 16; jj++){
                float s = rowp[jj];
                if (s > tv[4]){
                    float v0 = s; int i0 = k0 + jj;
                    #pragma unroll
                    for (int p = 0; p < 5; p++){
                        if (v0 > tv[p]){
                            float tpv = tv[p]; int tpi = tix[p];
                            tv[p] = v0; tix[p] = i0;
                            v0 = tpv; i0 = tpi;
                        }
                    }
                }
            }
        }
    }

    __syncthreads();
    float* mv = sm;                   // [64][20]
    int*   mx = (int*)(sm + 1280);    // [64][20]
    #pragma unroll
    for (int r = 0; r < 5; r++){
        mv[qq*20 + seg*5 + r] = tv[r];
        mx[qq*20 + seg*5 + r] = tix[r];
    }
    __syncthreads();
    if (t < 64){
        unsigned used = 0;
        int l = li*64 + t;
        for (int r = 0; r < 5; r++){
            float bvv = -3e38f; int bii = 0x7fffffff; int bc = 0;
            #pragma unroll
            for (int c = 0; c < 20; c++){
                if (used & (1u << c)) continue;
                float v = mv[t*20 + c]; int ii = mx[t*20 + c];
                if (v > bvv || (v == bvv && ii < bii)){ bvv = v; bii = ii; bc = c; }
            }
            used |= 1u << bc;
            g_pmv[((b*4 + sp)*5 + r)*LL + l] = bvv;
            g_pmi[((b*4 + sp)*5 + r)*LL + l] = bii;
        }
    }
}

// ---------------- K5b: merge 4 split lists into final ranks 1..4 ----------------
__global__ void topk_merge(){
    int b = blockIdx.y, li = blockIdx.x, q = threadIdx.x;  // 64 threads
    int l = li*64 + q;
    float mv[20]; int mx[20];
    #pragma unroll
    for (int sp = 0; sp < 4; sp++)
        #pragma unroll
        for (int r = 0; r < 5; r++){
            mv[sp*5 + r] = g_pmv[((b*4 + sp)*5 + r)*LL + l];
            mx[sp*5 + r] = g_pmi[((b*4 + sp)*5 + r)*LL + l];
        }
    unsigned used = 0;
    for (int r = 0; r < 5; r++){
        float bvv = -3e38f; int bii = 0x7fffffff; int bc = 0;
        #pragma unroll
        for (int c = 0; c < 20; c++){
            if (used & (1u << c)) continue;
            if (mv[c] > bvv || (mv[c] == bvv && mx[c] < bii)){ bvv = mv[c]; bii = mx[c]; bc = c; }
        }
        used |= 1u << bc;
        if (r >= 1){
            g_topv[(b*4 + (r-1))*LL + l] = bvv;
            g_topi[(b*4 + (r-1))*LL + l] = bii;
        }
    }
}

// ---------------- K6: gather (channels-last) + 1x1 convs, pixel-split x2 ----------------
__global__ __launch_bounds__(256, 2) void final_kernel(const float* __restrict__ x,
                             const float* __restrict__ wt1, const float* __restrict__ bt1,
                             const float* __restrict__ wt2, const float* __restrict__ bt2,
                             float* __restrict__ out){
    extern __shared__ float sm[];
    float* Tc   = sm;                    // [256][34] = 8704 (later aliased as fx[128][32])
    float* tex  = sm + 8704;             // [64][32]
    float* wbuf = sm + 10752;            // [64][64]
    float* msc  = sm + 14848;            // [4][32]
    int*   midx = (int*)(sm + 14976);    // [4][3][34]
    int b = blockIdx.x >> 6, i = blockIdx.x & 63;
    int h = blockIdx.y;
    int t = threadIdx.x;
    int j0 = (t & 15)*2, c0 = (t >> 4)*4;

    for (int e = t; e < 4*3*34; e += 256){
        int br = e / 102, rr = (e / 34) % 3, jo = e % 34;
        int li = i - 1 + rr, lj = h*32 - 1 + jo;
        int v = 0;
        if ((unsigned)li < 64u && (unsigned)lj < 64u)
            v = g_topi[(b*4 + br)*LL + li*64 + lj];
        midx[e] = v;
    }
    if (t < 128){
        int br = t >> 5, j = t & 31;
        msc[t] = g_topv[(b*4 + br)*LL + i*64 + h*32 + j];
    }
    __syncthreads();

    // gather: thread = (branch, channel); pixel index warp-uniform -> coalesced
    {
        int br = t >> 6, c = t & 63;
        const float* xT = &g_xpadT[(size_t)b*LP*CC];
        const int* mrow = &midx[br*102];
        for (int j = 0; j < 32; j++){
            int jj = h*32 + j;
            float sum = 0.f;
            #pragma unroll
            for (int kh = 0; kh < 3; kh++){
                int liq = i + 1 - kh;
                if ((unsigned)liq >= 64u) continue;
                int slot = 2 - kh;
                #pragma unroll
                for (int kw = 0; kw < 3; kw++){
                    int lj = jj + 1 - kw;
                    if ((unsigned)lj >= 64u) continue;
                    int m  = mrow[slot*34 + (lj - h*32 + 1)];
                    int mi = m >> 6, mj = m & 63;
                    sum += xT[(size_t)((mi + kh)*PW + mj + kw)*CC + c];
                }
            }
            Tc[(br*64 + c)*34 + j] = sum * msc[br*32 + j] * (1.0f/9.0f);
        }
    }

    // texture = wt1 @ Tcat + bt1  (K=256, staged weight chunks of 64)
    float a[4][2];
    #pragma unroll
    for (int ii = 0; ii < 4; ii++){ a[ii][0] = 0.f; a[ii][1] = 0.f; }
    for (int cc = 0; cc < 4; cc++){
        __syncthreads();
        for (int e = t; e < 4096; e += 256)
            wbuf[e] = wt1[(e >> 6)*256 + cc*64 + (e & 63)];
        __syncthreads();
        #pragma unroll 4
        for (int cil = 0; cil < 64; cil++){
            float2 v = *(const float2*)&Tc[(cc*64 + cil)*34 + j0];
            #pragma unroll
            for (int ii = 0; ii < 4; ii++){
                float wv = wbuf[(c0 + ii)*64 + cil];
                a[ii][0] += wv*v.x; a[ii][1] += wv*v.y;
            }
        }
    }
    #pragma unroll
    for (int ii = 0; ii < 4; ii++){
        float bv = __ldg(&bt1[c0 + ii]);
        *(float2*)&tex[(c0 + ii)*32 + j0] = make_float2(a[ii][0]+bv, a[ii][1]+bv);
    }
    __syncthreads();

    // load feature & x half-rows into Tc region (Tc dead)
    float* fx = Tc;
    for (int e = t; e < 64*32; e += 256){
        int cch = e >> 5, j = e & 31;
        fx[e]           = g_feature[((b*CC + cch)*HH + i)*WW + h*32 + j];
        fx[64*32 + e]   = x[((b*CC + cch)*HH + i)*WW + h*32 + j];
    }

    // y = wt2 @ [feature; x; texture] + bt2  (K=192, 3 chunks)
    float a2[4][2];
    #pragma unroll
    for (int ii = 0; ii < 4; ii++){ a2[ii][0] = 0.f; a2[ii][1] = 0.f; }
    for (int cc = 0; cc < 3; cc++){
        __syncthreads();
        for (int e = t; e < 4096; e += 256)
            wbuf[e] = wt2[(e >> 6)*192 + cc*64 + (e & 63)];
        __syncthreads();
        const float* src = (cc == 2) ? tex : fx + cc*2048;
        #pragma unroll 4
        for (int cil = 0; cil < 64; cil++){
            float2 v = *(const float2*)&src[cil*32 + j0];
            #pragma unroll
            for (int ii = 0; ii < 4; ii++){
                float wv = wbuf[(c0 + ii)*64 + cil];
                a2[ii][0] += wv*v.x; a2[ii][1] += wv*v.y;
            }
        }
    }
    #pragma unroll
    for (int ii = 0; ii < 4; ii++){
        float bv = __ldg(&bt2[c0 + ii]);
        *(float2*)&out[((b*CC + c0 + ii)*HH + i)*WW + h*32 + j0] =
            make_float2(a2[ii][0]+bv, a2[ii][1]+bv);
    }
}

// ---------------- launch ----------------
extern "C" void kernel_launch(void* const* d_in, const int* in_sizes, int n_in,
                              void* d_out, int out_size){
    const float* x   = (const float*)d_in[0];
    const float* w1  = (const float*)d_in[1];
    const float* b1  = (const float*)d_in[2];
    const float* w2  = (const float*)d_in[3];
    const float* b2  = (const float*)d_in[4];
    const float* wt1 = (const float*)d_in[5];
    const float* bt1 = (const float*)d_in[6];
    const float* wt2 = (const float*)d_in[7];
    const float* bt2 = (const float*)d_in[8];
    float* out = (float*)d_out;

    const int CONV_SMEM = (13056 + 9216)*4;        // 89088
    const int GEMM_SMEM = 128*133*4;               // 68096
    const int STK_SMEM  = (13464 + 128)*4;         // 54368
    const int FIN_SMEM  = (14976 + 408)*4;         // 61536

    static cudaStream_t sB = nullptr;
    static cudaEvent_t evFork = nullptr, evSim = nullptr, evJoin = nullptr;
    if (sB == nullptr){
        cudaStreamCreateWithFlags(&sB, cudaStreamNonBlocking);
        cudaEventCreateWithFlags(&evFork, cudaEventDisableTiming);
        cudaEventCreateWithFlags(&evSim,  cudaEventDisableTiming);
        cudaEventCreateWithFlags(&evJoin, cudaEventDisableTiming);
        cudaFuncSetAttribute(convg_kernel, cudaFuncAttributeMaxDynamicSharedMemorySize, CONV_SMEM);
        cudaFuncSetAttribute(gram_gemm,    cudaFuncAttributeMaxDynamicSharedMemorySize, GEMM_SMEM);
        cudaFuncSetAttribute(stopk_part,   cudaFuncAttributeMaxDynamicSharedMemorySize, STK_SMEM);
        cudaFuncSetAttribute(final_kernel, cudaFuncAttributeMaxDynamicSharedMemorySize, FIN_SMEM);
    }

    pad_kernel<<<dim3(66, 4), 256>>>(x);
    cudaEventRecord(evFork, 0);
    cudaStreamWaitEvent(sB, evFork, 0);

    // branch B: norms (needed by stopk), channels-last transpose + convs (needed by final)
    n2_kernel<<<dim3(18, 4), 256, 0, sB>>>();
    rn_kernel<<<dim3(64, 4), 64, 0, sB>>>();
    cudaEventRecord(evSim, sB);
    xt_kernel<<<dim3(69, 4), 256, 0, sB>>>();
    convg_kernel<<<dim3(64, 4), 256, CONV_SMEM, sB>>>(w1, b1, 0);
    convg_kernel<<<dim3(64, 4), 256, CONV_SMEM, sB>>>(w2, b2, 1);
    cudaEventRecord(evJoin, sB);

    // branch A (critical path): gram -> stopk -> merge
    gram_gemm<<<dim3(630, 4), 256, GEMM_SMEM>>>();
    cudaStreamWaitEvent(0, evSim, 0);
    stopk_part<<<dim3(4, 256), 256, STK_SMEM>>>();
    topk_merge<<<dim3(64, 4), 64>>>();

    cudaStreamWaitEvent(0, evJoin, 0);
    final_kernel<<<dim3(256, 2), 256, FIN_SMEM>>>(x, wt1, bt1, wt2, bt2, out);
}